// round 13
// baseline (speedup 1.0000x reference)
#include <cuda_runtime.h>

// NECTAR binning — 64x4 warp bands, 2 px/thread (low-register, high-occupancy).
// logits [16,4,512,512] f32, val_freqs [4,9,15] f32 -> out [16,4,512,512] f32.

#define H_DIM 512
#define W_DIM 512
#define HW    (H_DIM * W_DIM)
#define NTH   128                    // 4 warps; each warp = 64x4 band
#define BAND  4

__device__ __forceinline__ unsigned int argmax_w(float l0, float l1, float l2, float l3,
                                                 float& m) {
    m = l0; unsigned int w = 1u;
    if (l1 > m) { m = l1; w = 1u << 8;  }
    if (l2 > m) { m = l2; w = 1u << 16; }
    if (l3 > m) { m = l3; w = 1u << 24; }
    return w;
}

// contributions-only row (2 px)
__device__ __forceinline__ void row_cw(const float* __restrict__ pr, unsigned int cw[2]) {
    const float2 A  = *(const float2*)(pr);
    const float2 Bv = *(const float2*)(pr + HW);
    const float2 Cv = *(const float2*)(pr + 2 * HW);
    const float2 Dv = *(const float2*)(pr + 3 * HW);
    float m;
    cw[0] = argmax_w(A.x, Bv.x, Cv.x, Dv.x, m);
    cw[1] = argmax_w(A.y, Bv.y, Cv.y, Dv.y, m);
}

// full row (2 px): contributions + packed bins (guarded fast exp)
__device__ __forceinline__ void row_full2(const float* __restrict__ pr,
                                          unsigned int cw[2], unsigned int binw[2]) {
    const float2 A  = *(const float2*)(pr);
    const float2 Bv = *(const float2*)(pr + HW);
    const float2 Cv = *(const float2*)(pr + 2 * HW);
    const float2 Dv = *(const float2*)(pr + 3 * HW);
    const float p0[2] = {A.x, A.y};
    const float p1[2] = {Bv.x, Bv.y};
    const float p2[2] = {Cv.x, Cv.y};
    const float p3[2] = {Dv.x, Dv.y};
    const float bw = 1.0f / 15.0f;

    #pragma unroll
    for (int j = 0; j < 2; j++) {
        const float l0 = p0[j], l1 = p1[j], l2 = p2[j], l3 = p3[j];
        float m;
        cw[j] = argmax_w(l0, l1, l2, l3, m);

        // fast path (no max-subtract; mathematically identical softmax)
        const float e0 = __expf(l0);
        const float e1 = __expf(l1);
        const float e2 = __expf(l2);
        const float e3 = __expf(l3);
        const float s  = e0 + e1 + e2 + e3;
        const float tt = __fdividef(15.0f, s);
        const float u0 = e0 * tt, u1 = e1 * tt, u2 = e2 * tt, u3 = e3 * tt;
        int b0 = (int)u0, b1 = (int)u1, b2 = (int)u2, b3 = (int)u3;

        const float g = 1e-4f;   // fast-path |u| error bound ~2.3e-5 -> 4x margin
        const float d0 = fminf(fabsf(u0 - rintf(u0)), fabsf(u1 - rintf(u1)));
        const float d1 = fminf(fabsf(u2 - rintf(u2)), fabsf(u3 - rintf(u3)));
        if (fminf(d0, d1) < g) {
            // exact path: bit-validated reference formula
            const float a0 = expf(l0 - m);
            const float a1 = expf(l1 - m);
            const float a2 = expf(l2 - m);
            const float a3 = expf(l3 - m);
            const float as = a0 + a1 + a2 + a3;
            const float at = (1.0f / as) / bw;
            b0 = (int)(a0 * at);
            b1 = (int)(a1 * at);
            b2 = (int)(a2 * at);
            b3 = (int)(a3 * at);
        }
        b0 = b0 > 14 ? 14 : b0;
        b1 = b1 > 14 ? 14 : b1;
        b2 = b2 > 14 ? 14 : b2;
        b3 = b3 > 14 ? 14 : b3;
        const unsigned int t0 = __byte_perm((unsigned)b0, (unsigned)b1, 0x0040);
        const unsigned int t1 = __byte_perm((unsigned)b2, (unsigned)b3, 0x0040);
        binw[j] = __byte_perm(t0, t1, 0x5410);
    }
}

__device__ __forceinline__ unsigned int halo_w(const float* __restrict__ pb,
                                               int gy, bool doit, int dx) {
    if (!doit) return 0u;
    const float* hp = pb + (unsigned)gy * W_DIM + dx;
    const float l0 = __ldg(hp);
    const float l1 = __ldg(hp + HW);
    const float l2 = __ldg(hp + 2 * HW);
    const float l3 = __ldg(hp + 3 * HW);
    float m;
    return argmax_w(l0, l1, l2, l3, m);
}

// horizontal 3-windows for 2 px from lane-local cw + neighbor lanes
__device__ __forceinline__ void hwin(const unsigned int cw[2], unsigned int hw_,
                                     int lane, unsigned int W3[2]) {
    unsigned int prev = __shfl_up_sync(0xffffffffu, cw[1], 1);
    if (lane == 0)  prev = hw_;
    unsigned int nxt  = __shfl_down_sync(0xffffffffu, cw[0], 1);
    if (lane == 31) nxt = hw_;
    const unsigned int c01 = cw[0] + cw[1];
    W3[0] = prev + c01;
    W3[1] = c01  + nxt;
}

__device__ __forceinline__ void emit_row(float* __restrict__ po,
                                         const unsigned int S[2], const unsigned int W3[2],
                                         const unsigned int binsp[2],
                                         const float* __restrict__ s_vf) {
    float o0[2], o1[2], o2[2], o3[2];
    #pragma unroll
    for (int j = 0; j < 2; j++) {
        const unsigned int acc = S[j] + W3[j];
        const unsigned int idx = acc * 15u + binsp[j];   // per-byte 15*cnt+bin <= 134
        const float f0 = s_vf[        ( idx         & 0xFFu)];
        const float f1 = s_vf[135u + ((idx >> 8)    & 0xFFu)];
        const float f2 = s_vf[270u + ((idx >> 16)   & 0xFFu)];
        const float f3 = s_vf[405u + ( idx >> 24          )];
        float s = f0 + f1 + f2 + f3;
        s = (s == 0.0f) ? 1.0f : s;
        const float inv = __fdividef(1.0f, s);
        o0[j] = f0 * inv; o1[j] = f1 * inv; o2[j] = f2 * inv; o3[j] = f3 * inv;
    }
    __stcs((float2*)(po),          make_float2(o0[0], o0[1]));
    __stcs((float2*)(po + HW),     make_float2(o1[0], o1[1]));
    __stcs((float2*)(po + 2 * HW), make_float2(o2[0], o2[1]));
    __stcs((float2*)(po + 3 * HW), make_float2(o3[0], o3[1]));
}

__global__ __launch_bounds__(NTH, 10)    // cap regs ~51 -> up to 10 CTAs/SM
void nectar_binning_kernel(const float* __restrict__ logits,
                           const float* __restrict__ val_freqs,
                           float* __restrict__ out)
{
    __shared__ float s_vf[540];
    const int tid  = threadIdx.x;
    const int lane = tid & 31;
    const int wrp  = tid >> 5;

    for (int i = tid; i < 540; i += NTH) s_vf[i] = val_freqs[i];
    __syncthreads();

    const int x0    = blockIdx.x * 64;
    const int ybase = (blockIdx.y * 4 + wrp) * BAND;
    const unsigned int boff = blockIdx.z * 4u * HW;

    const float* pb = logits + boff + (unsigned)x0 + 2u * (unsigned)lane;
    float*       ob = out    + boff + (unsigned)x0 + 2u * (unsigned)lane;

    const bool edgeLane = (lane == 0) | (lane == 31);
    const bool haloOk   = edgeLane & ((lane == 0) ? (x0 > 0) : (x0 + 64 < W_DIM));
    const int  haloDx   = (lane == 0) ? -1 : 2;

    unsigned int cw[2], binw[2], W3p[2], W3[2], S[2], binsp[2];

    // ---- row -1 (top halo, contributions only) ----
    {
        const int gy = ybase - 1;
        const bool v = (gy >= 0);
        if (v) row_cw(pb + (unsigned)gy * W_DIM, cw);
        else { cw[0] = cw[1] = 0u; }
        const unsigned int hw_ = halo_w(pb, gy, haloOk & v, haloDx);
        hwin(cw, hw_, lane, W3p);
    }

    // ---- row 0 (full) ----
    {
        row_full2(pb + (unsigned)ybase * W_DIM, cw, binw);
        const unsigned int hw_ = halo_w(pb, ybase, haloOk, haloDx);
        hwin(cw, hw_, lane, W3);
        #pragma unroll
        for (int j = 0; j < 2; j++) {
            S[j]     = W3p[j] + (W3[j] - cw[j]);
            W3p[j]   = W3[j];
            binsp[j] = binw[j];
        }
    }

    // ---- rows 1..BAND-1 (full; each emits row r-1), fully unrolled ----
    #pragma unroll
    for (int r = 1; r <= BAND - 1; ++r) {
        const int gy = ybase + r;
        row_full2(pb + (unsigned)gy * W_DIM, cw, binw);
        const unsigned int hw_ = halo_w(pb, gy, haloOk, haloDx);
        hwin(cw, hw_, lane, W3);
        emit_row(ob + (unsigned)(gy - 1) * W_DIM, S, W3, binsp, s_vf);
        #pragma unroll
        for (int j = 0; j < 2; j++) {
            S[j]     = W3p[j] + (W3[j] - cw[j]);
            W3p[j]   = W3[j];
            binsp[j] = binw[j];
        }
    }

    // ---- row BAND (bottom halo, contributions only) + emit row BAND-1 ----
    {
        const int gy = ybase + BAND;
        const bool v = (gy < H_DIM);
        if (v) row_cw(pb + (unsigned)gy * W_DIM, cw);
        else { cw[0] = cw[1] = 0u; }
        const unsigned int hw_ = halo_w(pb, gy, haloOk & v, haloDx);
        hwin(cw, hw_, lane, W3);
        emit_row(ob + (unsigned)(ybase + BAND - 1) * W_DIM, S, W3, binsp, s_vf);
    }
}

extern "C" void kernel_launch(void* const* d_in, const int* in_sizes, int n_in,
                              void* d_out, int out_size)
{
    const float* logits    = (const float*)d_in[0];
    const float* val_freqs = (const float*)d_in[1];
    float*       out       = (float*)d_out;

    const int B = in_sizes[0] / (4 * HW);            // 16

    dim3 grid(W_DIM / 64, H_DIM / (4 * BAND), B);    // 8 x 32 x 16 = 4096 CTAs
    nectar_binning_kernel<<<grid, NTH>>>(logits, val_freqs, out);
}